// round 1
// baseline (speedup 1.0000x reference)
#include <cuda_runtime.h>
#include <cuda_bf16.h>
#include <math.h>

#define NN 100000
#define NE 1600000
#define FIN 128
#define FE 16
#define HH 64
#define TT 32
#define NI (NE + NN)   // edges + self loops

// ---------------- scratch (device globals; no runtime alloc) ----------------
__device__ __align__(16) float g_h[NN * HH];     // h = x @ W (current layer)
__device__ __align__(16) float g_acc[NN * HH];   // unnormalized aggregation
__device__ __align__(16) float g_feat[NN * HH];  // layer output (relu'd)
__device__ float g_hs[NN];
__device__ float g_hd[NN];
__device__ float g_z[NN];
__device__ float g_deg[NN];
__device__ __align__(16) float g_loop[NN * FE];  // self-loop edge attr (mean)
__device__ float g_p[NI];                        // exp(leaky(alpha)) per item
__device__ float g_et[2][NE];                    // edge_attr . (We@ae), per layer
__device__ float g_weae[2][FE];
__device__ float g_eloop[2][NN];                 // loop_attr . (We@ae)

// ---------------- tiny precompute: we_ae = We @ a_e (per layer) -------------
__global__ void k_weae(const float* We1, const float* ae1,
                       const float* We2, const float* ae2) {
    int t = threadIdx.x;
    if (t < FE) {
        float s = 0.f;
        for (int h = 0; h < HH; h++) s += We1[t * HH + h] * ae1[h];
        g_weae[0][t] = s;
    } else if (t < 2 * FE) {
        int f = t - FE;
        float s = 0.f;
        for (int h = 0; h < HH; h++) s += We2[f * HH + h] * ae2[h];
        g_weae[1][f] = s;
    }
}

__global__ void k_zero_pre() {
    int idx = blockIdx.x * blockDim.x + threadIdx.x;
    int stride = gridDim.x * blockDim.x;
    for (int i = idx; i < NN; i += stride) g_deg[i] = 0.f;
    for (int i = idx; i < NN * FE; i += stride) g_loop[i] = 0.f;
}

// single pass over edge_attr (102MB): degree, loop sums, and both eterm arrays
__global__ void k_edge_pre(const float* __restrict__ ea, const int* __restrict__ dst) {
    int e = blockIdx.x * blockDim.x + threadIdx.x;
    if (e >= NE) return;
    int d = dst[e];
    atomicAdd(&g_deg[d], 1.f);
    const float4* v = (const float4*)(ea + (size_t)e * FE);
    float4 a0 = v[0], a1 = v[1], a2 = v[2], a3 = v[3];
    float4* lp = (float4*)(g_loop + (size_t)d * FE);
    atomicAdd(lp + 0, a0);
    atomicAdd(lp + 1, a1);
    atomicAdd(lp + 2, a2);
    atomicAdd(lp + 3, a3);
    float av[16] = {a0.x, a0.y, a0.z, a0.w, a1.x, a1.y, a1.z, a1.w,
                    a2.x, a2.y, a2.z, a2.w, a3.x, a3.y, a3.z, a3.w};
    float s0 = 0.f, s1 = 0.f;
#pragma unroll
    for (int f = 0; f < FE; f++) {
        s0 += av[f] * g_weae[0][f];
        s1 += av[f] * g_weae[1][f];
    }
    g_et[0][e] = s0;
    g_et[1][e] = s1;
}

__global__ void k_loopfin() {
    int i = blockIdx.x * blockDim.x + threadIdx.x;
    if (i >= NN) return;
    float inv = 1.f / fmaxf(g_deg[i], 1.f);
    float s0 = 0.f, s1 = 0.f;
#pragma unroll
    for (int f = 0; f < FE; f++) {
        float v = g_loop[i * FE + f] * inv;
        s0 += v * g_weae[0][f];
        s1 += v * g_weae[1][f];
    }
    g_eloop[0][i] = s0;
    g_eloop[1][i] = s1;
}

__global__ void k_zero_layer() {
    int idx = blockIdx.x * blockDim.x + threadIdx.x;
    int stride = gridDim.x * blockDim.x;
    for (int i = idx; i < NN; i += stride) g_z[i] = 0.f;
    for (int i = idx; i < NN * HH; i += stride) g_acc[i] = 0.f;
}

// h = x @ W  (Din = 128 or 64). 16 rows / block, W staged in smem.
__global__ __launch_bounds__(256) void k_gemm(const float* __restrict__ xin,
                                              const float* __restrict__ W,
                                              int Din, int useFeat) {
    __shared__ float Ws[FIN * HH];   // up to 32KB
    __shared__ float xs[16 * FIN];   // up to 8KB
    const float* x = useFeat ? g_feat : xin;
    int tid = threadIdx.x;
    int nW = Din * HH;
    for (int i = tid; i < nW; i += 256) Ws[i] = W[i];
    int row0 = blockIdx.x * 16;
    int nx = 16 * Din;
    for (int i = tid; i < nx; i += 256) {
        int r = row0 + i / Din;
        xs[i] = (r < NN) ? x[(size_t)r * Din + (i % Din)] : 0.f;
    }
    __syncthreads();
    int rb = tid >> 6;   // 0..3
    int c = tid & 63;
    float a0 = 0.f, a1 = 0.f, a2 = 0.f, a3 = 0.f;
    for (int k = 0; k < Din; k++) {
        float w = Ws[k * HH + c];
        a0 = fmaf(xs[(rb + 0) * Din + k], w, a0);
        a1 = fmaf(xs[(rb + 4) * Din + k], w, a1);
        a2 = fmaf(xs[(rb + 8) * Din + k], w, a2);
        a3 = fmaf(xs[(rb + 12) * Din + k], w, a3);
    }
    int row = row0 + rb;
    if (row < NN) g_h[(size_t)row * HH + c] = a0;
    if (row + 4 < NN) g_h[(size_t)(row + 4) * HH + c] = a1;
    if (row + 8 < NN) g_h[(size_t)(row + 8) * HH + c] = a2;
    if (row + 12 < NN) g_h[(size_t)(row + 12) * HH + c] = a3;
}

// hs[i] = h[i].a_s, hd[i] = h[i].a_d  (one warp per node)
__global__ void k_sdots(const float* __restrict__ a_s, const float* __restrict__ a_d) {
    int gt = blockIdx.x * blockDim.x + threadIdx.x;
    int node = gt >> 5;
    int lane = gt & 31;
    if (node >= NN) return;
    float h0 = g_h[(size_t)node * HH + lane];
    float h1 = g_h[(size_t)node * HH + 32 + lane];
    float ps = h0 * a_s[lane] + h1 * a_s[lane + 32];
    float pd = h0 * a_d[lane] + h1 * a_d[lane + 32];
#pragma unroll
    for (int o = 16; o; o >>= 1) {
        ps += __shfl_down_sync(0xffffffffu, ps, o);
        pd += __shfl_down_sync(0xffffffffu, pd, o);
    }
    if (lane == 0) { g_hs[node] = ps; g_hd[node] = pd; }
}

// p = exp(leaky_relu(alpha)); z[dst] += p.  (softmax shift-invariant: max skipped)
__global__ void k_alpha(const int* __restrict__ src, const int* __restrict__ dst, int layer) {
    int idx = blockIdx.x * blockDim.x + threadIdx.x;
    if (idx >= NI) return;
    float a;
    int d;
    if (idx < NE) {
        int s = src[idx];
        d = dst[idx];
        a = g_hs[s] + g_hd[d] + g_et[layer][idx];
    } else {
        int i = idx - NE;
        d = i;
        a = g_hs[i] + g_hd[i] + g_eloop[layer][i];
    }
    a = (a > 0.f) ? a : 0.2f * a;
    float p = expf(a);
    g_p[idx] = p;
    atomicAdd(&g_z[d], p);
}

// acc[dst] += p * h[src]   (8 threads per item, float4 vector reductions)
__global__ __launch_bounds__(256) void k_scatter(const int* __restrict__ src,
                                                 const int* __restrict__ dst) {
    long gt = (long)blockIdx.x * blockDim.x + threadIdx.x;
    int idx = (int)(gt >> 3);
    int part = (int)(gt & 7);
    if (idx >= NI) return;
    int s, d;
    if (idx < NE) { s = src[idx]; d = dst[idx]; }
    else          { s = d = idx - NE; }
    float p = g_p[idx];
    const float4* hv = (const float4*)(g_h + (size_t)s * HH);
    float4* av = (float4*)(g_acc + (size_t)d * HH);
    float4 v0 = hv[part * 2 + 0];
    float4 v1 = hv[part * 2 + 1];
    atomicAdd(av + part * 2 + 0, make_float4(p * v0.x, p * v0.y, p * v0.z, p * v0.w));
    atomicAdd(av + part * 2 + 1, make_float4(p * v1.x, p * v1.y, p * v1.z, p * v1.w));
}

// feat = relu(acc / z + b)
__global__ void k_finalize(const float* __restrict__ b) {
    int idx = blockIdx.x * blockDim.x + threadIdx.x;
    if (idx >= NN * HH) return;
    int i = idx >> 6;
    int c = idx & 63;
    float v = g_acc[idx] / g_z[i] + b[c];
    g_feat[idx] = (v > 0.f) ? v : 0.f;
}

// classifier: relu(feat@Wc1+bc1)@Wc2+bc2, 8 nodes/block
__global__ __launch_bounds__(256) void k_mlp(const float* __restrict__ Wc1,
                                             const float* __restrict__ bc1,
                                             const float* __restrict__ Wc2,
                                             const float* __restrict__ bc2,
                                             float* __restrict__ out) {
    __shared__ float W1s[HH * 32];
    __shared__ float W2s[32 * TT];
    __shared__ float b1s[32], b2s[TT];
    __shared__ float fs[8 * HH];
    __shared__ float hid[8 * 32];
    int tid = threadIdx.x;
    for (int i = tid; i < HH * 32; i += 256) W1s[i] = Wc1[i];
    for (int i = tid; i < 32 * TT; i += 256) W2s[i] = Wc2[i];
    if (tid < 32) b1s[tid] = bc1[tid];
    else if (tid < 64) b2s[tid - 32] = bc2[tid - 32];
    int node0 = blockIdx.x * 8;
    for (int i = tid; i < 8 * HH; i += 256) {
        int r = node0 + i / HH;
        fs[i] = (r < NN) ? g_feat[(size_t)r * HH + (i % HH)] : 0.f;
    }
    __syncthreads();
    int ln = tid >> 5;
    int j = tid & 31;
    float acc = b1s[j];
#pragma unroll
    for (int k = 0; k < HH; k++) acc = fmaf(fs[ln * HH + k], W1s[k * 32 + j], acc);
    hid[ln * 32 + j] = fmaxf(acc, 0.f);
    __syncthreads();
    float lg = b2s[j];
#pragma unroll
    for (int k = 0; k < 32; k++) lg = fmaf(hid[ln * 32 + k], W2s[k * TT + j], lg);
    int node = node0 + ln;
    if (node < NN) out[(size_t)node * TT + j] = lg;
}

extern "C" void kernel_launch(void* const* d_in, const int* in_sizes, int n_in,
                              void* d_out, int out_size) {
    const float* x   = (const float*)d_in[0];
    const int*   ei  = (const int*)d_in[1];
    const float* ea  = (const float*)d_in[2];
    const float* W1  = (const float*)d_in[3];
    const float* as1 = (const float*)d_in[4];
    const float* ad1 = (const float*)d_in[5];
    const float* We1 = (const float*)d_in[6];
    const float* ae1 = (const float*)d_in[7];
    const float* b1  = (const float*)d_in[8];
    const float* W2  = (const float*)d_in[9];
    const float* as2 = (const float*)d_in[10];
    const float* ad2 = (const float*)d_in[11];
    const float* We2 = (const float*)d_in[12];
    const float* ae2 = (const float*)d_in[13];
    const float* b2  = (const float*)d_in[14];
    const float* Wc1 = (const float*)d_in[15];
    const float* bc1 = (const float*)d_in[16];
    const float* Wc2 = (const float*)d_in[17];
    const float* bc2 = (const float*)d_in[18];
    float* out = (float*)d_out;

    const int* src = ei;
    const int* dst = ei + NE;

    k_weae<<<1, 32>>>(We1, ae1, We2, ae2);
    k_zero_pre<<<2048, 256>>>();
    k_edge_pre<<<(NE + 255) / 256, 256>>>(ea, dst);
    k_loopfin<<<(NN + 255) / 256, 256>>>();

    // ---- layer 1 ----
    k_zero_layer<<<4096, 256>>>();
    k_gemm<<<(NN + 15) / 16, 256>>>(x, W1, FIN, 0);
    k_sdots<<<(NN * 32 + 255) / 256, 256>>>(as1, ad1);
    k_alpha<<<(NI + 255) / 256, 256>>>(src, dst, 0);
    k_scatter<<<(int)(((long)NI * 8 + 255) / 256), 256>>>(src, dst);
    k_finalize<<<(NN * HH + 255) / 256, 256>>>(b1);

    // ---- layer 2 ----
    k_zero_layer<<<4096, 256>>>();
    k_gemm<<<(NN + 15) / 16, 256>>>(nullptr, W2, HH, 1);
    k_sdots<<<(NN * 32 + 255) / 256, 256>>>(as2, ad2);
    k_alpha<<<(NI + 255) / 256, 256>>>(src, dst, 1);
    k_scatter<<<(int)(((long)NI * 8 + 255) / 256), 256>>>(src, dst);
    k_finalize<<<(NN * HH + 255) / 256, 256>>>(b2);

    // ---- classifier ----
    k_mlp<<<(NN + 7) / 8, 256>>>(Wc1, bc1, Wc2, bc2, out);
}

// round 2
// speedup vs baseline: 1.3512x; 1.3512x over previous
#include <cuda_runtime.h>
#include <cuda_bf16.h>
#include <math.h>

#define NN 100000
#define NE 1600000
#define FIN 128
#define FE 16
#define HH 64
#define TT 32
#define SCAN_B 1024
#define NBLK ((NN + SCAN_B - 1) / SCAN_B)   // 98

// ---------------- scratch (device globals; no runtime alloc) ----------------
__device__ __align__(16) float g_h[NN * HH];     // h = x @ W (current layer)
__device__ __align__(16) float g_feat[NN * HH];  // layer output (relu'd)
__device__ float g_hs[NN];
__device__ float g_hd[NN];
__device__ int   g_degi[NN];
__device__ __align__(16) float g_loop[NN * FE];  // self-loop edge attr sums
__device__ int   g_row[NN + 1];                  // CSR row offsets
__device__ int   g_cursor[NN];                   // fill cursors
__device__ int   g_bsum[NBLK];
__device__ int   g_boff[NBLK];
__device__ int   g_csr_src[NE];                  // src ids grouped by dst
__device__ float g_cet0[NE];                     // edge term layer1 (CSR order)
__device__ float g_cet1[NE];                     // edge term layer2 (CSR order)
__device__ float g_weae[2][FE];
__device__ float g_eloop[2][NN];                 // self-loop edge term

// ---------------- tiny precompute: we_ae = We @ a_e (per layer) -------------
__global__ void k_weae(const float* We1, const float* ae1,
                       const float* We2, const float* ae2) {
    int t = threadIdx.x;
    if (t < FE) {
        float s = 0.f;
        for (int h = 0; h < HH; h++) s += We1[t * HH + h] * ae1[h];
        g_weae[0][t] = s;
    } else if (t < 2 * FE) {
        int f = t - FE;
        float s = 0.f;
        for (int h = 0; h < HH; h++) s += We2[f * HH + h] * ae2[h];
        g_weae[1][f] = s;
    }
}

__global__ void k_zero_pre() {
    int idx = blockIdx.x * blockDim.x + threadIdx.x;
    int stride = gridDim.x * blockDim.x;
    for (int i = idx; i < NN; i += stride) g_degi[i] = 0;
    for (int i = idx; i < NN * FE; i += stride) g_loop[i] = 0.f;
}

__global__ void k_deg(const int* __restrict__ dst) {
    int e = blockIdx.x * blockDim.x + threadIdx.x;
    if (e < NE) atomicAdd(&g_degi[dst[e]], 1);
}

// ---- 3-kernel exclusive scan of g_degi -> g_row / g_cursor ----
__global__ void k_scan_part() {
    __shared__ int wsum[32];
    int tid = threadIdx.x, lane = tid & 31, wid = tid >> 5;
    int idx = blockIdx.x * SCAN_B + tid;
    int v = (idx < NN) ? g_degi[idx] : 0;
    int x = v;
#pragma unroll
    for (int o = 1; o < 32; o <<= 1) { int y = __shfl_up_sync(~0u, x, o); if (lane >= o) x += y; }
    if (lane == 31) wsum[wid] = x;
    __syncthreads();
    if (wid == 0) {
        int s = wsum[lane];
#pragma unroll
        for (int o = 1; o < 32; o <<= 1) { int y = __shfl_up_sync(~0u, s, o); if (lane >= o) s += y; }
        wsum[lane] = s;
    }
    __syncthreads();
    int off = wid ? wsum[wid - 1] : 0;
    if (idx < NN) g_row[idx] = x - v + off;
    if (tid == SCAN_B - 1) g_bsum[blockIdx.x] = off + x;
}

__global__ void k_scan_tops() {
    __shared__ int sh[NBLK];
    int tid = threadIdx.x;
    if (tid < NBLK) sh[tid] = g_bsum[tid];
    __syncthreads();
    if (tid == 0) {
        int run = 0;
        for (int i = 0; i < NBLK; i++) { int t = sh[i]; sh[i] = run; run += t; }
        g_row[NN] = run;
    }
    __syncthreads();
    if (tid < NBLK) g_boff[tid] = sh[tid];
}

__global__ void k_scan_add() {
    int idx = blockIdx.x * SCAN_B + threadIdx.x;
    if (idx < NN) {
        int r = g_row[idx] + g_boff[blockIdx.x];
        g_row[idx] = r;
        g_cursor[idx] = r;
    }
}

// single pass over edge_attr (102MB): loop sums, edge terms -> CSR slots
__global__ void k_edge_pre(const float* __restrict__ ea, const int* __restrict__ src,
                           const int* __restrict__ dst) {
    int e = blockIdx.x * blockDim.x + threadIdx.x;
    if (e >= NE) return;
    int d = dst[e];
    const float4* v = (const float4*)(ea + (size_t)e * FE);
    float4 a0 = v[0], a1 = v[1], a2 = v[2], a3 = v[3];
    float4* lp = (float4*)(g_loop + (size_t)d * FE);
    atomicAdd(lp + 0, a0);
    atomicAdd(lp + 1, a1);
    atomicAdd(lp + 2, a2);
    atomicAdd(lp + 3, a3);
    float av[16] = {a0.x, a0.y, a0.z, a0.w, a1.x, a1.y, a1.z, a1.w,
                    a2.x, a2.y, a2.z, a2.w, a3.x, a3.y, a3.z, a3.w};
    float s0 = 0.f, s1 = 0.f;
#pragma unroll
    for (int f = 0; f < FE; f++) {
        s0 += av[f] * g_weae[0][f];
        s1 += av[f] * g_weae[1][f];
    }
    int pos = atomicAdd(&g_cursor[d], 1);
    g_csr_src[pos] = src[e];
    g_cet0[pos] = s0;
    g_cet1[pos] = s1;
}

__global__ void k_loopfin() {
    int i = blockIdx.x * blockDim.x + threadIdx.x;
    if (i >= NN) return;
    float inv = 1.f / fmaxf((float)g_degi[i], 1.f);
    float s0 = 0.f, s1 = 0.f;
#pragma unroll
    for (int f = 0; f < FE; f++) {
        float v = g_loop[i * FE + f] * inv;
        s0 += v * g_weae[0][f];
        s1 += v * g_weae[1][f];
    }
    g_eloop[0][i] = s0;
    g_eloop[1][i] = s1;
}

// h = x @ W  (Din = 128 or 64). 32 rows / block, W staged in smem.
__global__ __launch_bounds__(256) void k_gemm(const float* __restrict__ xin,
                                              const float* __restrict__ W,
                                              int Din, int useFeat) {
    __shared__ float Ws[FIN * HH];   // up to 32KB
    __shared__ float xs[32 * FIN];   // up to 16KB
    const float* x = useFeat ? g_feat : xin;
    int tid = threadIdx.x;
    int nW = Din * HH;
    for (int i = tid; i < nW; i += 256) Ws[i] = W[i];
    int row0 = blockIdx.x * 32;
    int nx = 32 * Din;
    for (int i = tid; i < nx; i += 256) {
        int r = row0 + i / Din;
        xs[i] = (r < NN) ? x[(size_t)r * Din + (i % Din)] : 0.f;
    }
    __syncthreads();
    int rb = tid >> 6;   // 0..3
    int c = tid & 63;
    float acc[8] = {0.f, 0.f, 0.f, 0.f, 0.f, 0.f, 0.f, 0.f};
    for (int k = 0; k < Din; k++) {
        float w = Ws[k * HH + c];
#pragma unroll
        for (int r = 0; r < 8; r++)
            acc[r] = fmaf(xs[(rb + 4 * r) * Din + k], w, acc[r]);
    }
#pragma unroll
    for (int r = 0; r < 8; r++) {
        int row = row0 + rb + 4 * r;
        if (row < NN) g_h[(size_t)row * HH + c] = acc[r];
    }
}

// hs[i] = h[i].a_s, hd[i] = h[i].a_d  (one warp per node)
__global__ void k_sdots(const float* __restrict__ a_s, const float* __restrict__ a_d) {
    int gt = blockIdx.x * blockDim.x + threadIdx.x;
    int node = gt >> 5;
    int lane = gt & 31;
    if (node >= NN) return;
    float h0 = g_h[(size_t)node * HH + lane];
    float h1 = g_h[(size_t)node * HH + 32 + lane];
    float ps = h0 * a_s[lane] + h1 * a_s[lane + 32];
    float pd = h0 * a_d[lane] + h1 * a_d[lane + 32];
#pragma unroll
    for (int o = 16; o; o >>= 1) {
        ps += __shfl_down_sync(0xffffffffu, ps, o);
        pd += __shfl_down_sync(0xffffffffu, pd, o);
    }
    if (lane == 0) { g_hs[node] = ps; g_hd[node] = pd; }
}

// One warp per dst node: inline softmax weights + gather-aggregate + bias + relu.
__global__ __launch_bounds__(256) void k_aggregate(const float* __restrict__ cet,
                                                   const float* __restrict__ eloop,
                                                   const float* __restrict__ b) {
    int node = blockIdx.x * 8 + (threadIdx.x >> 5);
    int lane = threadIdx.x & 31;
    if (node >= NN) return;
    int beg = g_row[node], end = g_row[node + 1];
    float hd_d = g_hd[node];
    float acc0 = 0.f, acc1 = 0.f, z = 0.f;
    for (int base = beg; base < end; base += 32) {
        int i = base + lane;
        int s = 0;
        float p = 0.f;
        if (i < end) {
            s = g_csr_src[i];
            float a = g_hs[s] + hd_d + cet[i];
            a = (a > 0.f) ? a : 0.2f * a;
            p = __expf(a);
            z += p;
        }
        int cnt = min(32, end - base);
        for (int j = 0; j < cnt; j++) {
            float pj = __shfl_sync(0xffffffffu, p, j);
            int sj = __shfl_sync(0xffffffffu, s, j);
            acc0 += pj * g_h[(size_t)sj * HH + lane];
            acc1 += pj * g_h[(size_t)sj * HH + 32 + lane];
        }
    }
#pragma unroll
    for (int o = 16; o; o >>= 1) z += __shfl_xor_sync(0xffffffffu, z, o);
    // self loop
    float al = g_hs[node] + hd_d + eloop[node];
    al = (al > 0.f) ? al : 0.2f * al;
    float pl = __expf(al);
    z += pl;
    acc0 += pl * g_h[(size_t)node * HH + lane];
    acc1 += pl * g_h[(size_t)node * HH + 32 + lane];
    float inv = 1.f / z;
    g_feat[(size_t)node * HH + lane]      = fmaxf(fmaf(acc0, inv, b[lane]), 0.f);
    g_feat[(size_t)node * HH + 32 + lane] = fmaxf(fmaf(acc1, inv, b[lane + 32]), 0.f);
}

// classifier: relu(feat@Wc1+bc1)@Wc2+bc2, 8 nodes/block
__global__ __launch_bounds__(256) void k_mlp(const float* __restrict__ Wc1,
                                             const float* __restrict__ bc1,
                                             const float* __restrict__ Wc2,
                                             const float* __restrict__ bc2,
                                             float* __restrict__ out) {
    __shared__ float W1s[HH * 32];
    __shared__ float W2s[32 * TT];
    __shared__ float b1s[32], b2s[TT];
    __shared__ float fs[8 * HH];
    __shared__ float hid[8 * 32];
    int tid = threadIdx.x;
    for (int i = tid; i < HH * 32; i += 256) W1s[i] = Wc1[i];
    for (int i = tid; i < 32 * TT; i += 256) W2s[i] = Wc2[i];
    if (tid < 32) b1s[tid] = bc1[tid];
    else if (tid < 64) b2s[tid - 32] = bc2[tid - 32];
    int node0 = blockIdx.x * 8;
    for (int i = tid; i < 8 * HH; i += 256) {
        int r = node0 + i / HH;
        fs[i] = (r < NN) ? g_feat[(size_t)r * HH + (i % HH)] : 0.f;
    }
    __syncthreads();
    int ln = tid >> 5;
    int j = tid & 31;
    float acc = b1s[j];
#pragma unroll
    for (int k = 0; k < HH; k++) acc = fmaf(fs[ln * HH + k], W1s[k * 32 + j], acc);
    hid[ln * 32 + j] = fmaxf(acc, 0.f);
    __syncthreads();
    float lg = b2s[j];
#pragma unroll
    for (int k = 0; k < 32; k++) lg = fmaf(hid[ln * 32 + k], W2s[k * TT + j], lg);
    int node = node0 + ln;
    if (node < NN) out[(size_t)node * TT + j] = lg;
}

extern "C" void kernel_launch(void* const* d_in, const int* in_sizes, int n_in,
                              void* d_out, int out_size) {
    const float* x   = (const float*)d_in[0];
    const int*   ei  = (const int*)d_in[1];
    const float* ea  = (const float*)d_in[2];
    const float* W1  = (const float*)d_in[3];
    const float* as1 = (const float*)d_in[4];
    const float* ad1 = (const float*)d_in[5];
    const float* We1 = (const float*)d_in[6];
    const float* ae1 = (const float*)d_in[7];
    const float* b1  = (const float*)d_in[8];
    const float* W2  = (const float*)d_in[9];
    const float* as2 = (const float*)d_in[10];
    const float* ad2 = (const float*)d_in[11];
    const float* We2 = (const float*)d_in[12];
    const float* ae2 = (const float*)d_in[13];
    const float* b2  = (const float*)d_in[14];
    const float* Wc1 = (const float*)d_in[15];
    const float* bc1 = (const float*)d_in[16];
    const float* Wc2 = (const float*)d_in[17];
    const float* bc2 = (const float*)d_in[18];
    float* out = (float*)d_out;

    const int* src = ei;
    const int* dst = ei + NE;

    float *d_cet0, *d_cet1, *d_el0, *d_el1;
    cudaGetSymbolAddress((void**)&d_cet0, g_cet0);
    cudaGetSymbolAddress((void**)&d_cet1, g_cet1);
    cudaGetSymbolAddress((void**)&d_el0, g_eloop);
    d_el1 = d_el0 + NN;

    k_weae<<<1, 32>>>(We1, ae1, We2, ae2);
    k_zero_pre<<<2048, 256>>>();
    k_deg<<<(NE + 255) / 256, 256>>>(dst);
    k_scan_part<<<NBLK, SCAN_B>>>();
    k_scan_tops<<<1, 128>>>();
    k_scan_add<<<NBLK, SCAN_B>>>();
    k_edge_pre<<<(NE + 255) / 256, 256>>>(ea, src, dst);
    k_loopfin<<<(NN + 255) / 256, 256>>>();

    // ---- layer 1 ----
    k_gemm<<<(NN + 31) / 32, 256>>>(x, W1, FIN, 0);
    k_sdots<<<(NN * 32 + 255) / 256, 256>>>(as1, ad1);
    k_aggregate<<<(NN + 7) / 8, 256>>>(d_cet0, d_el0, b1);

    // ---- layer 2 ----
    k_gemm<<<(NN + 31) / 32, 256>>>(nullptr, W2, HH, 1);
    k_sdots<<<(NN * 32 + 255) / 256, 256>>>(as2, ad2);
    k_aggregate<<<(NN + 7) / 8, 256>>>(d_cet1, d_el1, b2);

    // ---- classifier ----
    k_mlp<<<(NN + 7) / 8, 256>>>(Wc1, bc1, Wc2, bc2, out);
}

// round 3
// speedup vs baseline: 1.5708x; 1.1626x over previous
#include <cuda_runtime.h>
#include <cuda_bf16.h>
#include <math.h>

#define NN 100000
#define NE 1600000
#define FIN 128
#define FE 16
#define HH 64
#define TT 32
#define SCAN_B 1024
#define NBLK ((NN + SCAN_B - 1) / SCAN_B)   // 98
#define GEMM_BLKS 1184

// ---------------- scratch (device globals; no runtime alloc) ----------------
__device__ __align__(16) float g_h[NN * HH];     // h = x @ W (current layer)
__device__ __align__(16) float g_feat[NN * HH];  // layer output (relu'd)
__device__ float g_hs[NN];
__device__ float g_hd[NN];
__device__ int   g_degi[NN];
__device__ float g_els[2 * NN];                  // per-dst sums of edge term (both layers)
__device__ int   g_row[NN + 1];                  // CSR row offsets
__device__ int   g_cursor[NN];                   // fill cursors
__device__ int   g_bsum[NBLK];
__device__ int   g_boff[NBLK];
__device__ int   g_csr_src[NE];                  // src ids grouped by dst
__device__ float g_cet0[NE];                     // edge term layer1 (CSR order)
__device__ float g_cet1[NE];                     // edge term layer2 (CSR order)
__device__ float g_weae[2][FE];
__device__ float g_eloop[2][NN];                 // self-loop edge term

// ---------------- tiny precompute: we_ae = We @ a_e (per layer) -------------
__global__ void k_weae(const float* We1, const float* ae1,
                       const float* We2, const float* ae2) {
    int t = threadIdx.x;
    if (t < FE) {
        float s = 0.f;
        for (int h = 0; h < HH; h++) s += We1[t * HH + h] * ae1[h];
        g_weae[0][t] = s;
    } else if (t < 2 * FE) {
        int f = t - FE;
        float s = 0.f;
        for (int h = 0; h < HH; h++) s += We2[f * HH + h] * ae2[h];
        g_weae[1][f] = s;
    }
}

__global__ void k_zero_pre() {
    int idx = blockIdx.x * blockDim.x + threadIdx.x;
    int stride = gridDim.x * blockDim.x;
    for (int i = idx; i < NN; i += stride) g_degi[i] = 0;
    for (int i = idx; i < 2 * NN; i += stride) g_els[i] = 0.f;
}

__global__ void k_deg(const int* __restrict__ dst) {
    int e = blockIdx.x * blockDim.x + threadIdx.x;
    if (e < NE) atomicAdd(&g_degi[dst[e]], 1);
}

// ---- 3-kernel exclusive scan of g_degi -> g_row / g_cursor ----
__global__ void k_scan_part() {
    __shared__ int wsum[32];
    int tid = threadIdx.x, lane = tid & 31, wid = tid >> 5;
    int idx = blockIdx.x * SCAN_B + tid;
    int v = (idx < NN) ? g_degi[idx] : 0;
    int x = v;
#pragma unroll
    for (int o = 1; o < 32; o <<= 1) { int y = __shfl_up_sync(~0u, x, o); if (lane >= o) x += y; }
    if (lane == 31) wsum[wid] = x;
    __syncthreads();
    if (wid == 0) {
        int s = wsum[lane];
#pragma unroll
        for (int o = 1; o < 32; o <<= 1) { int y = __shfl_up_sync(~0u, s, o); if (lane >= o) s += y; }
        wsum[lane] = s;
    }
    __syncthreads();
    int off = wid ? wsum[wid - 1] : 0;
    if (idx < NN) g_row[idx] = x - v + off;
    if (tid == SCAN_B - 1) g_bsum[blockIdx.x] = off + x;
}

__global__ void k_scan_tops() {
    __shared__ int sh[NBLK];
    int tid = threadIdx.x;
    if (tid < NBLK) sh[tid] = g_bsum[tid];
    __syncthreads();
    if (tid == 0) {
        int run = 0;
        for (int i = 0; i < NBLK; i++) { int t = sh[i]; sh[i] = run; run += t; }
        g_row[NN] = run;
    }
    __syncthreads();
    if (tid < NBLK) g_boff[tid] = sh[tid];
}

__global__ void k_scan_add() {
    int idx = blockIdx.x * SCAN_B + threadIdx.x;
    if (idx < NN) {
        int r = g_row[idx] + g_boff[blockIdx.x];
        g_row[idx] = r;
        g_cursor[idx] = r;
    }
}

// single pass over edge_attr (102MB): scalar edge-term sums + CSR fill
__global__ void k_edge_pre(const float* __restrict__ ea, const int* __restrict__ src,
                           const int* __restrict__ dst) {
    int e = blockIdx.x * blockDim.x + threadIdx.x;
    if (e >= NE) return;
    int d = dst[e];
    const float4* v = (const float4*)(ea + (size_t)e * FE);
    float4 a0 = v[0], a1 = v[1], a2 = v[2], a3 = v[3];
    float av[16] = {a0.x, a0.y, a0.z, a0.w, a1.x, a1.y, a1.z, a1.w,
                    a2.x, a2.y, a2.z, a2.w, a3.x, a3.y, a3.z, a3.w};
    float s0 = 0.f, s1 = 0.f;
#pragma unroll
    for (int f = 0; f < FE; f++) {
        s0 += av[f] * g_weae[0][f];
        s1 += av[f] * g_weae[1][f];
    }
    atomicAdd(&g_els[2 * d], s0);
    atomicAdd(&g_els[2 * d + 1], s1);
    int pos = atomicAdd(&g_cursor[d], 1);
    g_csr_src[pos] = src[e];
    g_cet0[pos] = s0;
    g_cet1[pos] = s1;
}

__global__ void k_loopfin() {
    int i = blockIdx.x * blockDim.x + threadIdx.x;
    if (i >= NN) return;
    float inv = 1.f / fmaxf((float)g_degi[i], 1.f);
    g_eloop[0][i] = g_els[2 * i] * inv;
    g_eloop[1][i] = g_els[2 * i + 1] * inv;
}

// h = x @ W  (Din = 128 or 64). Persistent blocks, 32 rows / tile, W in smem once.
__global__ __launch_bounds__(256) void k_gemm(const float* __restrict__ xin,
                                              const float* __restrict__ W,
                                              int Din, int useFeat) {
    __shared__ __align__(16) float Ws[FIN * HH];   // up to 32KB
    __shared__ __align__(16) float xs[32 * FIN];   // up to 16KB
    const float* x = useFeat ? g_feat : xin;
    int tid = threadIdx.x;
    int nW = Din * HH;
    for (int i = tid; i < nW; i += 256) Ws[i] = W[i];
    int rb = tid >> 6;   // 0..3
    int c = tid & 63;
    int NT = (NN + 31) / 32;
    int nx = 32 * Din;
    for (int tile = blockIdx.x; tile < NT; tile += gridDim.x) {
        int row0 = tile * 32;
        __syncthreads();
        for (int i = tid; i < nx; i += 256) {
            int r = row0 + i / Din;
            xs[i] = (r < NN) ? x[(size_t)r * Din + (i % Din)] : 0.f;
        }
        __syncthreads();
        float acc[8] = {0.f, 0.f, 0.f, 0.f, 0.f, 0.f, 0.f, 0.f};
        for (int k = 0; k < Din; k += 4) {
            float w0 = Ws[(k + 0) * HH + c];
            float w1 = Ws[(k + 1) * HH + c];
            float w2 = Ws[(k + 2) * HH + c];
            float w3 = Ws[(k + 3) * HH + c];
#pragma unroll
            for (int r = 0; r < 8; r++) {
                float4 xv = *(const float4*)&xs[(rb + 4 * r) * Din + k];
                acc[r] = fmaf(xv.x, w0, fmaf(xv.y, w1, fmaf(xv.z, w2, fmaf(xv.w, w3, acc[r]))));
            }
        }
#pragma unroll
        for (int r = 0; r < 8; r++) {
            int row = row0 + rb + 4 * r;
            if (row < NN) g_h[(size_t)row * HH + c] = acc[r];
        }
    }
}

// hs[i] = h[i].a_s, hd[i] = h[i].a_d  (one warp per node, float2 loads)
__global__ void k_sdots(const float* __restrict__ a_s, const float* __restrict__ a_d) {
    int gt = blockIdx.x * blockDim.x + threadIdx.x;
    int node = gt >> 5;
    int lane = gt & 31;
    if (node >= NN) return;
    float2 v = ((const float2*)g_h)[(size_t)node * 32 + lane];
    float as0 = a_s[2 * lane], as1 = a_s[2 * lane + 1];
    float ad0 = a_d[2 * lane], ad1 = a_d[2 * lane + 1];
    float ps = v.x * as0 + v.y * as1;
    float pd = v.x * ad0 + v.y * ad1;
#pragma unroll
    for (int o = 16; o; o >>= 1) {
        ps += __shfl_down_sync(0xffffffffu, ps, o);
        pd += __shfl_down_sync(0xffffffffu, pd, o);
    }
    if (lane == 0) { g_hs[node] = ps; g_hd[node] = pd; }
}

// One warp per dst node: inline softmax weights + float2 gather + bias + relu.
__global__ __launch_bounds__(256) void k_aggregate(const float* __restrict__ cet,
                                                   const float* __restrict__ eloop,
                                                   const float* __restrict__ b) {
    int node = blockIdx.x * 8 + (threadIdx.x >> 5);
    int lane = threadIdx.x & 31;
    if (node >= NN) return;
    int beg = g_row[node], end = g_row[node + 1];
    float hd_d = g_hd[node];
    float ax = 0.f, ay = 0.f, z = 0.f;
    const float2* h2 = (const float2*)g_h;
    for (int base = beg; base < end; base += 32) {
        int i = base + lane;
        int s = 0;
        float p = 0.f;
        if (i < end) {
            s = g_csr_src[i];
            float a = g_hs[s] + hd_d + cet[i];
            a = (a > 0.f) ? a : 0.2f * a;
            p = __expf(a);
            z += p;
        }
        int cnt = min(32, end - base);
        int j = 0;
        for (; j + 4 <= cnt; j += 4) {
            float p0 = __shfl_sync(~0u, p, j + 0);
            float p1 = __shfl_sync(~0u, p, j + 1);
            float p2 = __shfl_sync(~0u, p, j + 2);
            float p3 = __shfl_sync(~0u, p, j + 3);
            int s0 = __shfl_sync(~0u, s, j + 0);
            int s1 = __shfl_sync(~0u, s, j + 1);
            int s2 = __shfl_sync(~0u, s, j + 2);
            int s3 = __shfl_sync(~0u, s, j + 3);
            float2 v0 = h2[(size_t)s0 * 32 + lane];
            float2 v1 = h2[(size_t)s1 * 32 + lane];
            float2 v2 = h2[(size_t)s2 * 32 + lane];
            float2 v3 = h2[(size_t)s3 * 32 + lane];
            ax += p0 * v0.x + p1 * v1.x + p2 * v2.x + p3 * v3.x;
            ay += p0 * v0.y + p1 * v1.y + p2 * v2.y + p3 * v3.y;
        }
        for (; j < cnt; j++) {
            float pj = __shfl_sync(~0u, p, j);
            int sj = __shfl_sync(~0u, s, j);
            float2 v = h2[(size_t)sj * 32 + lane];
            ax += pj * v.x;
            ay += pj * v.y;
        }
    }
#pragma unroll
    for (int o = 16; o; o >>= 1) z += __shfl_xor_sync(0xffffffffu, z, o);
    // self loop
    float al = g_hs[node] + hd_d + eloop[node];
    al = (al > 0.f) ? al : 0.2f * al;
    float pl = __expf(al);
    z += pl;
    float2 vs = h2[(size_t)node * 32 + lane];
    ax += pl * vs.x;
    ay += pl * vs.y;
    float inv = 1.f / z;
    float2 o2;
    o2.x = fmaxf(fmaf(ax, inv, b[2 * lane]), 0.f);
    o2.y = fmaxf(fmaf(ay, inv, b[2 * lane + 1]), 0.f);
    ((float2*)g_feat)[(size_t)node * 32 + lane] = o2;
}

// classifier: relu(feat@Wc1+bc1)@Wc2+bc2, 8 nodes/block
__global__ __launch_bounds__(256) void k_mlp(const float* __restrict__ Wc1,
                                             const float* __restrict__ bc1,
                                             const float* __restrict__ Wc2,
                                             const float* __restrict__ bc2,
                                             float* __restrict__ out) {
    __shared__ float W1s[HH * 32];
    __shared__ float W2s[32 * TT];
    __shared__ float b1s[32], b2s[TT];
    __shared__ float fs[8 * HH];
    __shared__ float hid[8 * 32];
    int tid = threadIdx.x;
    for (int i = tid; i < HH * 32; i += 256) W1s[i] = Wc1[i];
    for (int i = tid; i < 32 * TT; i += 256) W2s[i] = Wc2[i];
    if (tid < 32) b1s[tid] = bc1[tid];
    else if (tid < 64) b2s[tid - 32] = bc2[tid - 32];
    int node0 = blockIdx.x * 8;
    for (int i = tid; i < 8 * HH; i += 256) {
        int r = node0 + i / HH;
        fs[i] = (r < NN) ? g_feat[(size_t)r * HH + (i % HH)] : 0.f;
    }
    __syncthreads();
    int ln = tid >> 5;
    int j = tid & 31;
    float acc = b1s[j];
#pragma unroll
    for (int k = 0; k < HH; k++) acc = fmaf(fs[ln * HH + k], W1s[k * 32 + j], acc);
    hid[ln * 32 + j] = fmaxf(acc, 0.f);
    __syncthreads();
    float lg = b2s[j];
#pragma unroll
    for (int k = 0; k < 32; k++) lg = fmaf(hid[ln * 32 + k], W2s[k * TT + j], lg);
    int node = node0 + ln;
    if (node < NN) out[(size_t)node * TT + j] = lg;
}

extern "C" void kernel_launch(void* const* d_in, const int* in_sizes, int n_in,
                              void* d_out, int out_size) {
    const float* x   = (const float*)d_in[0];
    const int*   ei  = (const int*)d_in[1];
    const float* ea  = (const float*)d_in[2];
    const float* W1  = (const float*)d_in[3];
    const float* as1 = (const float*)d_in[4];
    const float* ad1 = (const float*)d_in[5];
    const float* We1 = (const float*)d_in[6];
    const float* ae1 = (const float*)d_in[7];
    const float* b1  = (const float*)d_in[8];
    const float* W2  = (const float*)d_in[9];
    const float* as2 = (const float*)d_in[10];
    const float* ad2 = (const float*)d_in[11];
    const float* We2 = (const float*)d_in[12];
    const float* ae2 = (const float*)d_in[13];
    const float* b2  = (const float*)d_in[14];
    const float* Wc1 = (const float*)d_in[15];
    const float* bc1 = (const float*)d_in[16];
    const float* Wc2 = (const float*)d_in[17];
    const float* bc2 = (const float*)d_in[18];
    float* out = (float*)d_out;

    const int* src = ei;
    const int* dst = ei + NE;

    float *d_cet0, *d_cet1, *d_el0, *d_el1;
    cudaGetSymbolAddress((void**)&d_cet0, g_cet0);
    cudaGetSymbolAddress((void**)&d_cet1, g_cet1);
    cudaGetSymbolAddress((void**)&d_el0, g_eloop);
    d_el1 = d_el0 + NN;

    k_weae<<<1, 32>>>(We1, ae1, We2, ae2);
    k_zero_pre<<<512, 256>>>();
    k_deg<<<(NE + 255) / 256, 256>>>(dst);
    k_scan_part<<<NBLK, SCAN_B>>>();
    k_scan_tops<<<1, 128>>>();
    k_scan_add<<<NBLK, SCAN_B>>>();
    k_edge_pre<<<(NE + 255) / 256, 256>>>(ea, src, dst);
    k_loopfin<<<(NN + 255) / 256, 256>>>();

    // ---- layer 1 ----
    k_gemm<<<GEMM_BLKS, 256>>>(x, W1, FIN, 0);
    k_sdots<<<(NN * 32 + 255) / 256, 256>>>(as1, ad1);
    k_aggregate<<<(NN + 7) / 8, 256>>>(d_cet0, d_el0, b1);

    // ---- layer 2 ----
    k_gemm<<<GEMM_BLKS, 256>>>(nullptr, W2, HH, 1);
    k_sdots<<<(NN * 32 + 255) / 256, 256>>>(as2, ad2);
    k_aggregate<<<(NN + 7) / 8, 256>>>(d_cet1, d_el1, b2);

    // ---- classifier ----
    k_mlp<<<(NN + 7) / 8, 256>>>(Wc1, bc1, Wc2, bc2, out);
}

// round 4
// speedup vs baseline: 1.9392x; 1.2345x over previous
#include <cuda_runtime.h>
#include <cuda_fp16.h>
#include <math.h>

#define NN 100000
#define NE 1600000
#define FIN 128
#define FE 16
#define HH 64
#define TT 32
#define SCAN_B 1024
#define NBLK ((NN + SCAN_B - 1) / SCAN_B)   // 98

// ---------------- scratch (device globals; no runtime alloc) ----------------
__device__ __align__(16) __half2 g_h16[NN * 32]; // h in fp16 (gather table)
__device__ __align__(16) float g_feat[NN * HH];  // layer output (relu'd)
__device__ float g_hs[NN];
__device__ float g_hd[NN];
__device__ int   g_degi[NN];
__device__ int   g_row[NN + 1];                  // CSR row offsets
__device__ int   g_cursor[NN];                   // fill cursors
__device__ int   g_bsum[NBLK];
__device__ int   g_boff[NBLK];
__device__ int   g_csr_src[NE];                  // src ids grouped by dst
__device__ float g_cet0[NE];                     // edge term layer1 (CSR order)
__device__ float g_cet1[NE];                     // edge term layer2 (CSR order)
__device__ float g_weae[2][FE];

// ---------------- tiny precompute: we_ae = We @ a_e (per layer) -------------
__global__ void k_weae(const float* We1, const float* ae1,
                       const float* We2, const float* ae2) {
    int t = threadIdx.x;
    if (t < FE) {
        float s = 0.f;
        for (int h = 0; h < HH; h++) s += We1[t * HH + h] * ae1[h];
        g_weae[0][t] = s;
    } else if (t < 2 * FE) {
        int f = t - FE;
        float s = 0.f;
        for (int h = 0; h < HH; h++) s += We2[f * HH + h] * ae2[h];
        g_weae[1][f] = s;
    }
}

__global__ void k_zero_pre() {
    int idx = blockIdx.x * blockDim.x + threadIdx.x;
    if (idx < NN) g_degi[idx] = 0;
}

__global__ void k_deg(const int* __restrict__ dst) {
    int e = blockIdx.x * blockDim.x + threadIdx.x;
    if (e < NE) atomicAdd(&g_degi[dst[e]], 1);
}

// ---- 3-kernel exclusive scan of g_degi -> g_row / g_cursor ----
__global__ void k_scan_part() {
    __shared__ int wsum[32];
    int tid = threadIdx.x, lane = tid & 31, wid = tid >> 5;
    int idx = blockIdx.x * SCAN_B + tid;
    int v = (idx < NN) ? g_degi[idx] : 0;
    int x = v;
#pragma unroll
    for (int o = 1; o < 32; o <<= 1) { int y = __shfl_up_sync(~0u, x, o); if (lane >= o) x += y; }
    if (lane == 31) wsum[wid] = x;
    __syncthreads();
    if (wid == 0) {
        int s = wsum[lane];
#pragma unroll
        for (int o = 1; o < 32; o <<= 1) { int y = __shfl_up_sync(~0u, s, o); if (lane >= o) s += y; }
        wsum[lane] = s;
    }
    __syncthreads();
    int off = wid ? wsum[wid - 1] : 0;
    if (idx < NN) g_row[idx] = x - v + off;
    if (tid == SCAN_B - 1) g_bsum[blockIdx.x] = off + x;
}

__global__ void k_scan_tops() {
    __shared__ int sh[NBLK];
    int tid = threadIdx.x;
    if (tid < NBLK) sh[tid] = g_bsum[tid];
    __syncthreads();
    if (tid == 0) {
        int run = 0;
        for (int i = 0; i < NBLK; i++) { int t = sh[i]; sh[i] = run; run += t; }
        g_row[NN] = run;
    }
    __syncthreads();
    if (tid < NBLK) g_boff[tid] = sh[tid];
}

__global__ void k_scan_add() {
    int idx = blockIdx.x * SCAN_B + threadIdx.x;
    if (idx < NN) {
        int r = g_row[idx] + g_boff[blockIdx.x];
        g_row[idx] = r;
        g_cursor[idx] = r;
    }
}

// single pass over edge_attr (102MB): edge terms -> CSR slots
__global__ void k_edge_pre(const float* __restrict__ ea, const int* __restrict__ src,
                           const int* __restrict__ dst) {
    int e = blockIdx.x * blockDim.x + threadIdx.x;
    if (e >= NE) return;
    int d = dst[e];
    const float4* v = (const float4*)(ea + (size_t)e * FE);
    float4 a0 = v[0], a1 = v[1], a2 = v[2], a3 = v[3];
    float av[16] = {a0.x, a0.y, a0.z, a0.w, a1.x, a1.y, a1.z, a1.w,
                    a2.x, a2.y, a2.z, a2.w, a3.x, a3.y, a3.z, a3.w};
    float s0 = 0.f, s1 = 0.f;
#pragma unroll
    for (int f = 0; f < FE; f++) {
        s0 += av[f] * g_weae[0][f];
        s1 += av[f] * g_weae[1][f];
    }
    int pos = atomicAdd(&g_cursor[d], 1);
    g_csr_src[pos] = src[e];
    g_cet0[pos] = s0;
    g_cet1[pos] = s1;
}

// h = x @ W, 64x64 tile, 4x4 per thread. Epilogue fuses hs/hd dots + fp16 store.
template <int DIN>
__global__ __launch_bounds__(256) void k_gemm(const float* __restrict__ x,
                                              const float* __restrict__ W,
                                              const float* __restrict__ a_s,
                                              const float* __restrict__ a_d) {
    __shared__ __align__(16) float xs[DIN * 68];   // xs[k*68 + r], padded stride
    __shared__ __align__(16) float Ws[DIN * 64];
    int tid = threadIdx.x;
    int row0 = blockIdx.x * 64;
    for (int i = tid; i < DIN * 64; i += 256) Ws[i] = W[i];
    for (int i = tid; i < 64 * DIN; i += 256) {
        int r = i / DIN, k = i % DIN;   // consecutive tid -> consecutive k (coalesced)
        int rr = row0 + r;
        xs[k * 68 + r] = (rr < NN) ? x[(size_t)rr * DIN + k] : 0.f;
    }
    __syncthreads();
    int rg = tid >> 4, cg = tid & 15;
    float acc[4][4] = {};
#pragma unroll 4
    for (int k = 0; k < DIN; k++) {
        float4 xv = *(const float4*)&xs[k * 68 + 4 * rg];
        float4 wv = *(const float4*)&Ws[k * 64 + 4 * cg];
        acc[0][0] = fmaf(xv.x, wv.x, acc[0][0]);
        acc[0][1] = fmaf(xv.x, wv.y, acc[0][1]);
        acc[0][2] = fmaf(xv.x, wv.z, acc[0][2]);
        acc[0][3] = fmaf(xv.x, wv.w, acc[0][3]);
        acc[1][0] = fmaf(xv.y, wv.x, acc[1][0]);
        acc[1][1] = fmaf(xv.y, wv.y, acc[1][1]);
        acc[1][2] = fmaf(xv.y, wv.z, acc[1][2]);
        acc[1][3] = fmaf(xv.y, wv.w, acc[1][3]);
        acc[2][0] = fmaf(xv.z, wv.x, acc[2][0]);
        acc[2][1] = fmaf(xv.z, wv.y, acc[2][1]);
        acc[2][2] = fmaf(xv.z, wv.z, acc[2][2]);
        acc[2][3] = fmaf(xv.z, wv.w, acc[2][3]);
        acc[3][0] = fmaf(xv.w, wv.x, acc[3][0]);
        acc[3][1] = fmaf(xv.w, wv.y, acc[3][1]);
        acc[3][2] = fmaf(xv.w, wv.z, acc[3][2]);
        acc[3][3] = fmaf(xv.w, wv.w, acc[3][3]);
    }
    float myas[4], myad[4];
#pragma unroll
    for (int j = 0; j < 4; j++) { myas[j] = a_s[4 * cg + j]; myad[j] = a_d[4 * cg + j]; }
#pragma unroll
    for (int i = 0; i < 4; i++) {
        int row = row0 + 4 * rg + i;
        float hs = acc[i][0] * myas[0] + acc[i][1] * myas[1] +
                   acc[i][2] * myas[2] + acc[i][3] * myas[3];
        float hd = acc[i][0] * myad[0] + acc[i][1] * myad[1] +
                   acc[i][2] * myad[2] + acc[i][3] * myad[3];
#pragma unroll
        for (int o = 1; o < 16; o <<= 1) {
            hs += __shfl_xor_sync(~0u, hs, o);
            hd += __shfl_xor_sync(~0u, hd, o);
        }
        if (row < NN) {
            if (cg == 0) { g_hs[row] = hs; g_hd[row] = hd; }
            __half2* hp = &g_h16[(size_t)row * 32 + 2 * cg];
            hp[0] = __floats2half2_rn(acc[i][0], acc[i][1]);
            hp[1] = __floats2half2_rn(acc[i][2], acc[i][3]);
        }
    }
}

// One warp per dst node: softmax weights + fp16 gather + loop-term + bias + relu.
__global__ __launch_bounds__(256) void k_aggregate(const float* __restrict__ cet,
                                                   const float* __restrict__ b) {
    int node = blockIdx.x * 8 + (threadIdx.x >> 5);
    int lane = threadIdx.x & 31;
    if (node >= NN) return;
    int beg = g_row[node], end = g_row[node + 1];
    float hd_d = g_hd[node];
    float ax = 0.f, ay = 0.f, z = 0.f, cs = 0.f;
    for (int base = beg; base < end; base += 32) {
        int i = base + lane;
        int s = 0;
        float p = 0.f;
        if (i < end) {
            s = g_csr_src[i];
            float c = cet[i];
            cs += c;
            float a = g_hs[s] + hd_d + c;
            a = (a > 0.f) ? a : 0.2f * a;
            p = __expf(a);
            z += p;
        }
        int cnt = min(32, end - base);
        int j = 0;
        for (; j + 4 <= cnt; j += 4) {
            float p0 = __shfl_sync(~0u, p, j + 0);
            float p1 = __shfl_sync(~0u, p, j + 1);
            float p2 = __shfl_sync(~0u, p, j + 2);
            float p3 = __shfl_sync(~0u, p, j + 3);
            int s0 = __shfl_sync(~0u, s, j + 0);
            int s1 = __shfl_sync(~0u, s, j + 1);
            int s2 = __shfl_sync(~0u, s, j + 2);
            int s3 = __shfl_sync(~0u, s, j + 3);
            float2 v0 = __half22float2(g_h16[(size_t)s0 * 32 + lane]);
            float2 v1 = __half22float2(g_h16[(size_t)s1 * 32 + lane]);
            float2 v2 = __half22float2(g_h16[(size_t)s2 * 32 + lane]);
            float2 v3 = __half22float2(g_h16[(size_t)s3 * 32 + lane]);
            ax += p0 * v0.x + p1 * v1.x + p2 * v2.x + p3 * v3.x;
            ay += p0 * v0.y + p1 * v1.y + p2 * v2.y + p3 * v3.y;
        }
        for (; j < cnt; j++) {
            float pj = __shfl_sync(~0u, p, j);
            int sj = __shfl_sync(~0u, s, j);
            float2 v = __half22float2(g_h16[(size_t)sj * 32 + lane]);
            ax += pj * v.x;
            ay += pj * v.y;
        }
    }
#pragma unroll
    for (int o = 16; o; o >>= 1) {
        z += __shfl_xor_sync(0xffffffffu, z, o);
        cs += __shfl_xor_sync(0xffffffffu, cs, o);
    }
    int deg = end - beg;
    float eloop = cs / fmaxf((float)deg, 1.f);
    float al = g_hs[node] + hd_d + eloop;
    al = (al > 0.f) ? al : 0.2f * al;
    float pl = __expf(al);
    z += pl;
    float2 vs = __half22float2(g_h16[(size_t)node * 32 + lane]);
    ax += pl * vs.x;
    ay += pl * vs.y;
    float inv = 1.f / z;
    float2 o2;
    o2.x = fmaxf(fmaf(ax, inv, b[2 * lane]), 0.f);
    o2.y = fmaxf(fmaf(ay, inv, b[2 * lane + 1]), 0.f);
    ((float2*)g_feat)[(size_t)node * 32 + lane] = o2;
}

// classifier: relu(feat@Wc1+bc1)@Wc2+bc2, 8 nodes/block
__global__ __launch_bounds__(256) void k_mlp(const float* __restrict__ Wc1,
                                             const float* __restrict__ bc1,
                                             const float* __restrict__ Wc2,
                                             const float* __restrict__ bc2,
                                             float* __restrict__ out) {
    __shared__ float W1s[HH * 32];
    __shared__ float W2s[32 * TT];
    __shared__ float b1s[32], b2s[TT];
    __shared__ float fs[8 * HH];
    __shared__ float hid[8 * 32];
    int tid = threadIdx.x;
    for (int i = tid; i < HH * 32; i += 256) W1s[i] = Wc1[i];
    for (int i = tid; i < 32 * TT; i += 256) W2s[i] = Wc2[i];
    if (tid < 32) b1s[tid] = bc1[tid];
    else if (tid < 64) b2s[tid - 32] = bc2[tid - 32];
    int node0 = blockIdx.x * 8;
    for (int i = tid; i < 8 * HH; i += 256) {
        int r = node0 + i / HH;
        fs[i] = (r < NN) ? g_feat[(size_t)r * HH + (i % HH)] : 0.f;
    }
    __syncthreads();
    int ln = tid >> 5;
    int j = tid & 31;
    float acc = b1s[j];
#pragma unroll
    for (int k = 0; k < HH; k++) acc = fmaf(fs[ln * HH + k], W1s[k * 32 + j], acc);
    hid[ln * 32 + j] = fmaxf(acc, 0.f);
    __syncthreads();
    float lg = b2s[j];
#pragma unroll
    for (int k = 0; k < 32; k++) lg = fmaf(hid[ln * 32 + k], W2s[k * TT + j], lg);
    int node = node0 + ln;
    if (node < NN) out[(size_t)node * TT + j] = lg;
}

extern "C" void kernel_launch(void* const* d_in, const int* in_sizes, int n_in,
                              void* d_out, int out_size) {
    const float* x   = (const float*)d_in[0];
    const int*   ei  = (const int*)d_in[1];
    const float* ea  = (const float*)d_in[2];
    const float* W1  = (const float*)d_in[3];
    const float* as1 = (const float*)d_in[4];
    const float* ad1 = (const float*)d_in[5];
    const float* We1 = (const float*)d_in[6];
    const float* ae1 = (const float*)d_in[7];
    const float* b1  = (const float*)d_in[8];
    const float* W2  = (const float*)d_in[9];
    const float* as2 = (const float*)d_in[10];
    const float* ad2 = (const float*)d_in[11];
    const float* We2 = (const float*)d_in[12];
    const float* ae2 = (const float*)d_in[13];
    const float* b2  = (const float*)d_in[14];
    const float* Wc1 = (const float*)d_in[15];
    const float* bc1 = (const float*)d_in[16];
    const float* Wc2 = (const float*)d_in[17];
    const float* bc2 = (const float*)d_in[18];
    float* out = (float*)d_out;

    const int* src = ei;
    const int* dst = ei + NE;

    float *d_cet0, *d_cet1, *d_feat;
    cudaGetSymbolAddress((void**)&d_cet0, g_cet0);
    cudaGetSymbolAddress((void**)&d_cet1, g_cet1);
    cudaGetSymbolAddress((void**)&d_feat, g_feat);

    k_weae<<<1, 32>>>(We1, ae1, We2, ae2);
    k_zero_pre<<<(NN + 255) / 256, 256>>>();
    k_deg<<<(NE + 255) / 256, 256>>>(dst);
    k_scan_part<<<NBLK, SCAN_B>>>();
    k_scan_tops<<<1, 128>>>();
    k_scan_add<<<NBLK, SCAN_B>>>();
    k_edge_pre<<<(NE + 255) / 256, 256>>>(ea, src, dst);

    // ---- layer 1 ----
    k_gemm<FIN><<<(NN + 63) / 64, 256>>>(x, W1, as1, ad1);
    k_aggregate<<<(NN + 7) / 8, 256>>>(d_cet0, b1);

    // ---- layer 2 ----
    k_gemm<HH><<<(NN + 63) / 64, 256>>>(d_feat, W2, as2, ad2);
    k_aggregate<<<(NN + 7) / 8, 256>>>(d_cet1, b2);

    // ---- classifier ----
    k_mlp<<<(NN + 7) / 8, 256>>>(Wc1, bc1, Wc2, bc2, out);
}

// round 5
// speedup vs baseline: 2.1126x; 1.0894x over previous
#include <cuda_runtime.h>
#include <cuda_fp16.h>
#include <math.h>

#define NN 100000
#define NE 1600000
#define FIN 128
#define FE 16
#define HH 64
#define TT 32
#define SCAN_B 1024
#define NBLK ((NN + SCAN_B - 1) / SCAN_B)   // 98

// ---------------- scratch (device globals; no runtime alloc) ----------------
__device__ __align__(16) __half2 g_h16[NN * 32]; // h in fp16 (gather table)
__device__ __align__(16) float g_feat[NN * HH];  // layer output (relu'd)
__device__ float g_hs[NN];
__device__ float g_hd[NN];
__device__ int   g_degi[NN];
__device__ int   g_row[NN + 1];                  // CSR row offsets
__device__ int   g_cursor[NN];                   // fill cursors
__device__ int   g_bsum[NBLK];
__device__ int   g_boff[NBLK];
__device__ int   g_csr_src[NE];                  // src ids grouped by dst
__device__ __align__(8) float2 g_cet[NE];        // edge terms (layer1, layer2), CSR order
__device__ float g_weae[2][FE];

// ---------------- tiny precompute: we_ae = We @ a_e (per layer) -------------
__global__ void k_weae(const float* We1, const float* ae1,
                       const float* We2, const float* ae2) {
    int t = threadIdx.x;
    if (t < FE) {
        float s = 0.f;
        for (int h = 0; h < HH; h++) s += We1[t * HH + h] * ae1[h];
        g_weae[0][t] = s;
    } else if (t < 2 * FE) {
        int f = t - FE;
        float s = 0.f;
        for (int h = 0; h < HH; h++) s += We2[f * HH + h] * ae2[h];
        g_weae[1][f] = s;
    }
}

__global__ void k_zero_pre() {
    int idx = blockIdx.x * blockDim.x + threadIdx.x;
    if (idx < NN) g_degi[idx] = 0;
}

__global__ void k_deg(const int* __restrict__ dst) {
    int e = blockIdx.x * blockDim.x + threadIdx.x;
    if (e < NE) atomicAdd(&g_degi[dst[e]], 1);
}

// ---- 3-kernel exclusive scan of g_degi -> g_row / g_cursor ----
__global__ void k_scan_part() {
    __shared__ int wsum[32];
    int tid = threadIdx.x, lane = tid & 31, wid = tid >> 5;
    int idx = blockIdx.x * SCAN_B + tid;
    int v = (idx < NN) ? g_degi[idx] : 0;
    int x = v;
#pragma unroll
    for (int o = 1; o < 32; o <<= 1) { int y = __shfl_up_sync(~0u, x, o); if (lane >= o) x += y; }
    if (lane == 31) wsum[wid] = x;
    __syncthreads();
    if (wid == 0) {
        int s = wsum[lane];
#pragma unroll
        for (int o = 1; o < 32; o <<= 1) { int y = __shfl_up_sync(~0u, s, o); if (lane >= o) s += y; }
        wsum[lane] = s;
    }
    __syncthreads();
    int off = wid ? wsum[wid - 1] : 0;
    if (idx < NN) g_row[idx] = x - v + off;
    if (tid == SCAN_B - 1) g_bsum[blockIdx.x] = off + x;
}

__global__ void k_scan_tops() {
    __shared__ int sh[NBLK];
    int tid = threadIdx.x;
    if (tid < NBLK) sh[tid] = g_bsum[tid];
    __syncthreads();
    if (tid == 0) {
        int run = 0;
        for (int i = 0; i < NBLK; i++) { int t = sh[i]; sh[i] = run; run += t; }
        g_row[NN] = run;
    }
    __syncthreads();
    if (tid < NBLK) g_boff[tid] = sh[tid];
}

__global__ void k_scan_add() {
    int idx = blockIdx.x * SCAN_B + threadIdx.x;
    if (idx < NN) {
        int r = g_row[idx] + g_boff[blockIdx.x];
        g_row[idx] = r;
        g_cursor[idx] = r;
    }
}

// single pass over edge_attr (102MB): edge terms -> CSR slots
__global__ void k_edge_pre(const float* __restrict__ ea, const int* __restrict__ src,
                           const int* __restrict__ dst) {
    int e = blockIdx.x * blockDim.x + threadIdx.x;
    if (e >= NE) return;
    int d = dst[e];
    const float4* v = (const float4*)(ea + (size_t)e * FE);
    float4 a0 = v[0], a1 = v[1], a2 = v[2], a3 = v[3];
    float av[16] = {a0.x, a0.y, a0.z, a0.w, a1.x, a1.y, a1.z, a1.w,
                    a2.x, a2.y, a2.z, a2.w, a3.x, a3.y, a3.z, a3.w};
    float s0 = 0.f, s1 = 0.f;
#pragma unroll
    for (int f = 0; f < FE; f++) {
        s0 += av[f] * g_weae[0][f];
        s1 += av[f] * g_weae[1][f];
    }
    int pos = atomicAdd(&g_cursor[d], 1);
    g_csr_src[pos] = src[e];
    g_cet[pos] = make_float2(s0, s1);
}

// h = x @ W, 64x64 tile, 4x4 per thread. Epilogue fuses hs/hd dots + fp16 store.
template <int DIN>
__global__ __launch_bounds__(256) void k_gemm(const float* __restrict__ x,
                                              const float* __restrict__ W,
                                              const float* __restrict__ a_s,
                                              const float* __restrict__ a_d) {
    __shared__ __align__(16) float xs[DIN * 68];   // xs[k*68 + r], padded stride
    __shared__ __align__(16) float Ws[DIN * 64];
    int tid = threadIdx.x;
    int row0 = blockIdx.x * 64;
    for (int i = tid; i < DIN * 64; i += 256) Ws[i] = W[i];
    for (int i = tid; i < 64 * DIN; i += 256) {
        int r = i / DIN, k = i % DIN;   // consecutive tid -> consecutive k (coalesced)
        int rr = row0 + r;
        xs[k * 68 + r] = (rr < NN) ? x[(size_t)rr * DIN + k] : 0.f;
    }
    __syncthreads();
    int rg = tid >> 4, cg = tid & 15;
    float acc[4][4] = {};
#pragma unroll 4
    for (int k = 0; k < DIN; k++) {
        float4 xv = *(const float4*)&xs[k * 68 + 4 * rg];
        float4 wv = *(const float4*)&Ws[k * 64 + 4 * cg];
        acc[0][0] = fmaf(xv.x, wv.x, acc[0][0]);
        acc[0][1] = fmaf(xv.x, wv.y, acc[0][1]);
        acc[0][2] = fmaf(xv.x, wv.z, acc[0][2]);
        acc[0][3] = fmaf(xv.x, wv.w, acc[0][3]);
        acc[1][0] = fmaf(xv.y, wv.x, acc[1][0]);
        acc[1][1] = fmaf(xv.y, wv.y, acc[1][1]);
        acc[1][2] = fmaf(xv.y, wv.z, acc[1][2]);
        acc[1][3] = fmaf(xv.y, wv.w, acc[1][3]);
        acc[2][0] = fmaf(xv.z, wv.x, acc[2][0]);
        acc[2][1] = fmaf(xv.z, wv.y, acc[2][1]);
        acc[2][2] = fmaf(xv.z, wv.z, acc[2][2]);
        acc[2][3] = fmaf(xv.z, wv.w, acc[2][3]);
        acc[3][0] = fmaf(xv.w, wv.x, acc[3][0]);
        acc[3][1] = fmaf(xv.w, wv.y, acc[3][1]);
        acc[3][2] = fmaf(xv.w, wv.z, acc[3][2]);
        acc[3][3] = fmaf(xv.w, wv.w, acc[3][3]);
    }
    float myas[4], myad[4];
#pragma unroll
    for (int j = 0; j < 4; j++) { myas[j] = a_s[4 * cg + j]; myad[j] = a_d[4 * cg + j]; }
#pragma unroll
    for (int i = 0; i < 4; i++) {
        int row = row0 + 4 * rg + i;
        float hs = acc[i][0] * myas[0] + acc[i][1] * myas[1] +
                   acc[i][2] * myas[2] + acc[i][3] * myas[3];
        float hd = acc[i][0] * myad[0] + acc[i][1] * myad[1] +
                   acc[i][2] * myad[2] + acc[i][3] * myad[3];
#pragma unroll
        for (int o = 1; o < 16; o <<= 1) {
            hs += __shfl_xor_sync(~0u, hs, o);
            hd += __shfl_xor_sync(~0u, hd, o);
        }
        if (row < NN) {
            if (cg == 0) { g_hs[row] = hs; g_hd[row] = hd; }
            __half2* hp = &g_h16[(size_t)row * 32 + 2 * cg];
            hp[0] = __floats2half2_rn(acc[i][0], acc[i][1]);
            hp[1] = __floats2half2_rn(acc[i][2], acc[i][3]);
        }
    }
}

// One warp per dst node: softmax weights + fp16 gather + loop-term + bias + relu.
template <int L>
__global__ __launch_bounds__(256) void k_aggregate(const float* __restrict__ b) {
    int node = blockIdx.x * 8 + (threadIdx.x >> 5);
    int lane = threadIdx.x & 31;
    if (node >= NN) return;
    int beg = g_row[node], end = g_row[node + 1];
    float hd_d = g_hd[node];
    float ax = 0.f, ay = 0.f, z = 0.f, cs = 0.f;
    for (int base = beg; base < end; base += 32) {
        int i = base + lane;
        int s = 0;
        float p = 0.f;
        if (i < end) {
            s = g_csr_src[i];
            float2 cv = g_cet[i];
            float c = (L == 0) ? cv.x : cv.y;
            cs += c;
            float a = g_hs[s] + hd_d + c;
            a = (a > 0.f) ? a : 0.2f * a;
            p = __expf(a);
            z += p;
        }
        int cnt = min(32, end - base);
        int j = 0;
        for (; j + 4 <= cnt; j += 4) {
            float p0 = __shfl_sync(~0u, p, j + 0);
            float p1 = __shfl_sync(~0u, p, j + 1);
            float p2 = __shfl_sync(~0u, p, j + 2);
            float p3 = __shfl_sync(~0u, p, j + 3);
            int s0 = __shfl_sync(~0u, s, j + 0);
            int s1 = __shfl_sync(~0u, s, j + 1);
            int s2 = __shfl_sync(~0u, s, j + 2);
            int s3 = __shfl_sync(~0u, s, j + 3);
            float2 v0 = __half22float2(g_h16[(size_t)s0 * 32 + lane]);
            float2 v1 = __half22float2(g_h16[(size_t)s1 * 32 + lane]);
            float2 v2 = __half22float2(g_h16[(size_t)s2 * 32 + lane]);
            float2 v3 = __half22float2(g_h16[(size_t)s3 * 32 + lane]);
            ax += p0 * v0.x + p1 * v1.x + p2 * v2.x + p3 * v3.x;
            ay += p0 * v0.y + p1 * v1.y + p2 * v2.y + p3 * v3.y;
        }
        for (; j < cnt; j++) {
            float pj = __shfl_sync(~0u, p, j);
            int sj = __shfl_sync(~0u, s, j);
            float2 v = __half22float2(g_h16[(size_t)sj * 32 + lane]);
            ax += pj * v.x;
            ay += pj * v.y;
        }
    }
#pragma unroll
    for (int o = 16; o; o >>= 1) {
        z += __shfl_xor_sync(0xffffffffu, z, o);
        cs += __shfl_xor_sync(0xffffffffu, cs, o);
    }
    int deg = end - beg;
    float eloop = cs / fmaxf((float)deg, 1.f);
    float al = g_hs[node] + hd_d + eloop;
    al = (al > 0.f) ? al : 0.2f * al;
    float pl = __expf(al);
    z += pl;
    float2 vs = __half22float2(g_h16[(size_t)node * 32 + lane]);
    ax += pl * vs.x;
    ay += pl * vs.y;
    float inv = 1.f / z;
    float2 o2;
    o2.x = fmaxf(fmaf(ax, inv, b[2 * lane]), 0.f);
    o2.y = fmaxf(fmaf(ay, inv, b[2 * lane + 1]), 0.f);
    ((float2*)g_feat)[(size_t)node * 32 + lane] = o2;
}

// classifier: relu(feat@Wc1+bc1)@Wc2+bc2, 32 nodes/block
__global__ __launch_bounds__(256) void k_mlp(const float* __restrict__ Wc1,
                                             const float* __restrict__ bc1,
                                             const float* __restrict__ Wc2,
                                             const float* __restrict__ bc2,
                                             float* __restrict__ out) {
    __shared__ float W1s[HH * 32];
    __shared__ float W2s[32 * TT];
    __shared__ float b1s[32], b2s[TT];
    __shared__ float fs[32 * HH];
    __shared__ float hid[32 * 32];
    int tid = threadIdx.x;
    for (int i = tid; i < HH * 32; i += 256) W1s[i] = Wc1[i];
    for (int i = tid; i < 32 * TT; i += 256) W2s[i] = Wc2[i];
    if (tid < 32) b1s[tid] = bc1[tid];
    else if (tid < 64) b2s[tid - 32] = bc2[tid - 32];
    int node0 = blockIdx.x * 32;
    for (int i = tid; i < 32 * HH; i += 256) {
        int r = node0 + i / HH;
        fs[i] = (r < NN) ? g_feat[(size_t)r * HH + (i % HH)] : 0.f;
    }
    __syncthreads();
    int w = tid >> 5;
    int j = tid & 31;
#pragma unroll
    for (int n = w; n < 32; n += 8) {
        float acc = b1s[j];
#pragma unroll
        for (int k = 0; k < HH; k++) acc = fmaf(fs[n * HH + k], W1s[k * 32 + j], acc);
        hid[n * 32 + j] = fmaxf(acc, 0.f);
    }
    __syncthreads();
#pragma unroll
    for (int n = w; n < 32; n += 8) {
        float lg = b2s[j];
#pragma unroll
        for (int k = 0; k < 32; k++) lg = fmaf(hid[n * 32 + k], W2s[k * TT + j], lg);
        int node = node0 + n;
        if (node < NN) out[(size_t)node * TT + j] = lg;
    }
}

extern "C" void kernel_launch(void* const* d_in, const int* in_sizes, int n_in,
                              void* d_out, int out_size) {
    const float* x   = (const float*)d_in[0];
    const int*   ei  = (const int*)d_in[1];
    const float* ea  = (const float*)d_in[2];
    const float* W1  = (const float*)d_in[3];
    const float* as1 = (const float*)d_in[4];
    const float* ad1 = (const float*)d_in[5];
    const float* We1 = (const float*)d_in[6];
    const float* ae1 = (const float*)d_in[7];
    const float* b1  = (const float*)d_in[8];
    const float* W2  = (const float*)d_in[9];
    const float* as2 = (const float*)d_in[10];
    const float* ad2 = (const float*)d_in[11];
    const float* We2 = (const float*)d_in[12];
    const float* ae2 = (const float*)d_in[13];
    const float* b2  = (const float*)d_in[14];
    const float* Wc1 = (const float*)d_in[15];
    const float* bc1 = (const float*)d_in[16];
    const float* Wc2 = (const float*)d_in[17];
    const float* bc2 = (const float*)d_in[18];
    float* out = (float*)d_out;

    const int* src = ei;
    const int* dst = ei + NE;

    float* d_feat;
    cudaGetSymbolAddress((void**)&d_feat, g_feat);

    static cudaStream_t s2 = nullptr;
    static cudaEvent_t evFork = nullptr, evJoin = nullptr;
    if (!s2) {
        cudaStreamCreateWithFlags(&s2, cudaStreamNonBlocking);
        cudaEventCreateWithFlags(&evFork, cudaEventDisableTiming);
        cudaEventCreateWithFlags(&evJoin, cudaEventDisableTiming);
    }

    // fork: GEMM1 is independent of the CSR build chain
    cudaEventRecord(evFork, 0);
    cudaStreamWaitEvent(s2, evFork, 0);

    k_weae<<<1, 32>>>(We1, ae1, We2, ae2);
    k_zero_pre<<<(NN + 255) / 256, 256>>>();
    k_deg<<<(NE + 255) / 256, 256>>>(dst);

    k_gemm<FIN><<<(NN + 63) / 64, 256, 0, s2>>>(x, W1, as1, ad1);   // 4th launch (profiled)
    cudaEventRecord(evJoin, s2);

    k_scan_part<<<NBLK, SCAN_B>>>();
    k_scan_tops<<<1, 128>>>();
    k_scan_add<<<NBLK, SCAN_B>>>();
    k_edge_pre<<<(NE + 255) / 256, 256>>>(ea, src, dst);

    // join: aggregate-1 needs both GEMM1 and the CSR arrays
    cudaStreamWaitEvent(0, evJoin, 0);

    // ---- layer 1 ----
    k_aggregate<0><<<(NN + 7) / 8, 256>>>(b1);

    // ---- layer 2 ----
    k_gemm<HH><<<(NN + 63) / 64, 256>>>(d_feat, W2, as2, ad2);
    k_aggregate<1><<<(NN + 7) / 8, 256>>>(b2);

    // ---- classifier ----
    k_mlp<<<(NN + 31) / 32, 256>>>(Wc1, bc1, Wc2, bc2, out);
}